// round 7
// baseline (speedup 1.0000x reference)
#include <cuda_runtime.h>
#include <cstdint>

// CostVolume: B=4, C=128, H=128, W=256, r=4, D=81
// out[b,k,h,w] = (1/81) * sum_c x1[b,c,h,w] * x2[b,c,h-i,w-j],  k=(9i+j) mod 81
//
// Block (8,4,9): tx = w-oct (8 px), ty = h row, tz = row-shift i = tz-4.
// 36 f32x2 accumulators/thread. 3-buffer cp.async pipeline (depth 2).
// XOR-swizzled smem (bank-conflict-free LDS.128), 64-bit packed FMA operands.

#define C_DIM 128
#define H_DIM 128
#define W_DIM 256
#define D_DIM 81

#define TH 4
#define TW 64
#define TH8 12
#define CC 4
#define NCHUNK 32
#define THREADS 288

#define RS2G 24                       // x2 row stride in 16B granules (96 floats)
#define RS1G 16                       // x1 row stride in granules (64 floats)
#define X2_GRAN (CC * TH8 * RS2G)     // 1152
#define X1_GRAN (CC * TH * RS1G)      // 256
#define SST_GRAN (X2_GRAN + X1_GRAN)  // 1408 granules = 22528 B
#define SST_BYTES (SST_GRAN * 16)
#define NBUF 3
#define SMEM_BYTES (NBUF * SST_BYTES) // 67584 B
#define CHUNK_STRIDE (CC * H_DIM * W_DIM)

static_assert(SMEM_BYTES <= 227 * 1024, "smem over budget");
static_assert(X2_GRAN / 4 * 3 == 864 && 864 == 3 * THREADS, "x2 granule split");

__device__ __forceinline__ int swz(int cg) { return cg ^ ((cg >> 3) & 1); }

__device__ __forceinline__ double pk(float lo, float hi) {
    double d;
    asm("mov.b64 %0, {%1, %2};" : "=d"(d) : "f"(lo), "f"(hi));
    return d;
}
__device__ __forceinline__ void fma2(double& d, double a, double b) {
    asm("fma.rn.f32x2 %0, %1, %2, %0;" : "+d"(d) : "d"(a), "d"(b));
}
__device__ __forceinline__ float2 unpk(double d) {
    float2 v;
    asm("mov.b64 {%0, %1}, %2;" : "=f"(v.x), "=f"(v.y) : "d"(d));
    return v;
}

extern __shared__ float4 smem4[];

__global__ __launch_bounds__(THREADS, 2) void cost_volume_kernel(
    const float* __restrict__ x1,
    const float* __restrict__ x2,
    float* __restrict__ out)
{
    const int tx = threadIdx.x;           // 0..7
    const int ty = threadIdx.y;           // 0..3
    const int tz = threadIdx.z;           // 0..8
    const int tid = tx + 8 * ty + 32 * tz;

    const int w0 = blockIdx.x * TW;
    const int h0 = blockIdx.y * TH;
    const int b  = blockIdx.z;

    const int h  = h0 + ty;
    const int wb = w0 + tx * 8;
    const int r2 = ty + 8 - tz;           // x2 tile row for this thread's i

    const uint32_t smem_base = (uint32_t)__cvta_generic_to_shared(smem4);

    // ---- staging setup: 1408 granules/stage; x2 = 864 (3*288), x1 = 256 ----
    const float* gp[3];
    uint32_t so[3];
    uint32_t ss[3];
#pragma unroll
    for (int u = 0; u < 3; u++) {
        const int gi  = tid + u * THREADS;        // 0..863
        const int row = gi / 18;                  // 0..47 (c*12 + r)
        const int cg  = gi - row * 18;            // 0..17
        so[u] = (uint32_t)((row * RS2G + swz(cg)) * 16);
        const int c  = row / TH8;
        const int r  = row - c * TH8;
        const int gh = h0 - 4 + r;
        const int gw = w0 - 4 + cg * 4;
        const bool v = (gh >= 0) && (gh < H_DIM) && (gw >= 0) && (gw <= W_DIM - 4);
        ss[u] = v ? 16u : 0u;
        gp[u] = x2 + (v ? ((((long)b * C_DIM + c) * H_DIM + gh) * W_DIM + gw) : 0);
    }
    const bool hasx1 = (tid < 256);
    const int  xrow  = tid >> 4;                  // 0..15 (c*4 + hr)
    const int  xcg   = tid & 15;
    const uint32_t sox = (uint32_t)((X2_GRAN + xrow * RS1G + swz(xcg)) * 16);
    const int  xc  = xrow >> 2;
    const int  xhr = xrow & 3;
    const float* gpx = x1 + ((((long)b * C_DIM + xc) * H_DIM + (h0 + xhr)) * W_DIM + (w0 + xcg * 4));

    // thread-constant swizzled quad offsets for compute-side loads
    const int sx0 = swz(2 * tx);
    const int sx1 = swz(2 * tx + 1);
    const int sq0 = swz(2 * tx);
    const int sq1 = swz(2 * tx + 1);
    const int sq2 = swz(2 * tx + 2);
    const int sq3 = swz(2 * tx + 3);

    // ---- accumulators ------------------------------------------------------
    double acc[9][4];
#pragma unroll
    for (int jj = 0; jj < 9; jj++)
#pragma unroll
        for (int t = 0; t < 4; t++)
            acc[jj][t] = 0.0;

    // ---- staging macro -----------------------------------------------------
#define STAGE(BUFI)                                                              \
    do {                                                                         \
        const uint32_t sb_ = smem_base + (uint32_t)(BUFI) * SST_BYTES;           \
        asm volatile("cp.async.cg.shared.global [%0], [%1], 16, %2;\n"           \
                     :: "r"(sb_ + so[0]), "l"(gp[0]), "r"(ss[0]));               \
        asm volatile("cp.async.cg.shared.global [%0], [%1], 16, %2;\n"           \
                     :: "r"(sb_ + so[1]), "l"(gp[1]), "r"(ss[1]));               \
        asm volatile("cp.async.cg.shared.global [%0], [%1], 16, %2;\n"           \
                     :: "r"(sb_ + so[2]), "l"(gp[2]), "r"(ss[2]));               \
        if (hasx1)                                                               \
            asm volatile("cp.async.cg.shared.global [%0], [%1], 16;\n"           \
                         :: "r"(sb_ + sox), "l"(gpx));                           \
        gp[0] += CHUNK_STRIDE; gp[1] += CHUNK_STRIDE; gp[2] += CHUNK_STRIDE;     \
        gpx += CHUNK_STRIDE;                                                     \
    } while (0)

    // ---- prologue: stage chunks 0 and 1 ------------------------------------
    STAGE(0);
    asm volatile("cp.async.commit_group;" ::: "memory");
    STAGE(1);
    asm volatile("cp.async.commit_group;" ::: "memory");

    // ---- main loop ---------------------------------------------------------
    int bi = 0;       // buffer holding chunk ch
    int pi = 2;       // buffer to prefetch into (chunk ch+2)
    for (int ch = 0; ch < NCHUNK; ch++) {
        asm volatile("cp.async.wait_group 1;" ::: "memory");
        __syncthreads();

        if (ch + 2 < NCHUNK) STAGE(pi);
        asm volatile("cp.async.commit_group;" ::: "memory");

        const float4* buf = smem4 + (size_t)bi * SST_GRAN;
#pragma unroll
        for (int c = 0; c < CC; c++) {
            const int x1g = X2_GRAN + (c * TH + ty) * RS1G;
            const float4 A0 = buf[x1g + sx0];
            const float4 A1 = buf[x1g + sx1];

            const int x2g = (c * TH8 + r2) * RS2G;
            const float4 W0 = buf[x2g + sq0];
            const float4 W1 = buf[x2g + sq1];
            const float4 W2 = buf[x2g + sq2];
            const float4 W3 = buf[x2g + sq3];

            double Ap[4];
            Ap[0] = pk(A0.x, A0.y); Ap[1] = pk(A0.z, A0.w);
            Ap[2] = pk(A1.x, A1.y); Ap[3] = pk(A1.z, A1.w);

            // even pairs: alias aligned register pairs (no MOVs)
            double E[8];
            E[0] = pk(W0.x, W0.y); E[1] = pk(W0.z, W0.w);
            E[2] = pk(W1.x, W1.y); E[3] = pk(W1.z, W1.w);
            E[4] = pk(W2.x, W2.y); E[5] = pk(W2.z, W2.w);
            E[6] = pk(W3.x, W3.y); E[7] = pk(W3.z, W3.w);

            // even jj
#pragma unroll
            for (int jj = 0; jj < 9; jj += 2) {
                const int m = jj >> 1;
                fma2(acc[jj][0], Ap[0], E[m + 0]);
                fma2(acc[jj][1], Ap[1], E[m + 1]);
                fma2(acc[jj][2], Ap[2], E[m + 2]);
                fma2(acc[jj][3], Ap[3], E[m + 3]);
            }

            // odd pairs: built once per channel (CSE'd)
            double O[7];
            O[0] = pk(W0.y, W0.z); O[1] = pk(W0.w, W1.x);
            O[2] = pk(W1.y, W1.z); O[3] = pk(W1.w, W2.x);
            O[4] = pk(W2.y, W2.z); O[5] = pk(W2.w, W3.x);
            O[6] = pk(W3.y, W3.z);

            // odd jj
#pragma unroll
            for (int jj = 1; jj < 9; jj += 2) {
                const int m = jj >> 1;
                fma2(acc[jj][0], Ap[0], O[m + 0]);
                fma2(acc[jj][1], Ap[1], O[m + 1]);
                fma2(acc[jj][2], Ap[2], O[m + 2]);
                fma2(acc[jj][3], Ap[3], O[m + 3]);
            }
        }

        bi = (bi + 1 == NBUF) ? 0 : bi + 1;
        pi = (pi + 1 == NBUF) ? 0 : pi + 1;
    }

    // ---- epilogue ----------------------------------------------------------
    const float invD = (float)(1.0 / 81.0);
    const int i_d = tz - 4;
#pragma unroll
    for (int jj = 0; jj < 9; jj++) {
        const int j_d = 4 - jj;
        int k = 9 * i_d + j_d;
        k %= D_DIM;
        if (k < 0) k += D_DIM;

        float* op = out + ((((long)b * D_DIM + k) * H_DIM + h) * W_DIM + wb);
        const float2 p0 = unpk(acc[jj][0]);
        const float2 p1 = unpk(acc[jj][1]);
        const float2 p2 = unpk(acc[jj][2]);
        const float2 p3 = unpk(acc[jj][3]);
        ((float4*)op)[0] = make_float4(p0.x * invD, p0.y * invD, p1.x * invD, p1.y * invD);
        ((float4*)op)[1] = make_float4(p2.x * invD, p2.y * invD, p3.x * invD, p3.y * invD);
    }
}

extern "C" void kernel_launch(void* const* d_in, const int* in_sizes, int n_in,
                              void* d_out, int out_size)
{
    const float* x1 = (const float*)d_in[0];
    const float* x2 = (const float*)d_in[1];
    float* out = (float*)d_out;

    cudaFuncSetAttribute(cost_volume_kernel,
                         cudaFuncAttributeMaxDynamicSharedMemorySize, SMEM_BYTES);

    dim3 block(8, TH, 9);                       // 288 threads
    dim3 grid(W_DIM / TW, H_DIM / TH, 4);       // 512 blocks
    cost_volume_kernel<<<grid, block, SMEM_BYTES>>>(x1, x2, out);
}

// round 8
// speedup vs baseline: 1.0680x; 1.0680x over previous
#include <cuda_runtime.h>
#include <cstdint>

// CostVolume: B=4, C=128, H=128, W=256, r=4, D=81
// out[b,k,h,w] = (1/81) * sum_c x1[b,c,h,w] * x2[b,c,h-i,w-j],  k=(9i+j) mod 81
//
// Block (8,4,9). 36 f32x2 accumulators/thread. 3-buffer cp.async pipeline.
// ld.shared.v2.b64 loads pair-aligned f32x2 operands directly (no pack MOVs);
// only 7 odd straddle-pairs per channel are built (2 MOVs each).

#define C_DIM 128
#define H_DIM 128
#define W_DIM 256
#define D_DIM 81

#define TH 4
#define TW 64
#define TH8 12
#define CC 4
#define NCHUNK 32
#define THREADS 288

#define RS2G 24                       // x2 row stride in 16B granules
#define RS1G 16                       // x1 row stride in granules
#define X2_GRAN (CC * TH8 * RS2G)     // 1152
#define X1_GRAN (CC * TH * RS1G)      // 256
#define SST_GRAN (X2_GRAN + X1_GRAN)  // 1408 granules = 22528 B
#define SST_BYTES (SST_GRAN * 16)
#define NBUF 3
#define SMEM_BYTES (NBUF * SST_BYTES) // 67584 B
#define CHUNK_STRIDE (CC * H_DIM * W_DIM)

static_assert(SMEM_BYTES <= 227 * 1024, "smem over budget");

__device__ __forceinline__ int swz(int cg) { return cg ^ ((cg >> 3) & 1); }

// one LDS.128 -> two pair-aligned 64-bit (f32x2) operands, zero MOVs
__device__ __forceinline__ void lds2(double& a, double& b, uint32_t addr) {
    asm("ld.shared.v2.b64 {%0, %1}, [%2];" : "=d"(a), "=d"(b) : "r"(addr));
}
// {hi(a), lo(b)} : unpacks alias (free), pack = 2 MOV32
__device__ __forceinline__ double dshift(double a, double b) {
    double r;
    asm("{\n\t"
        ".reg .b32 alo, ahi, blo, bhi;\n\t"
        "mov.b64 {alo, ahi}, %1;\n\t"
        "mov.b64 {blo, bhi}, %2;\n\t"
        "mov.b64 %0, {ahi, blo};\n\t"
        "}" : "=d"(r) : "d"(a), "d"(b));
    return r;
}
__device__ __forceinline__ void fma2(double& d, double a, double b) {
    asm("fma.rn.f32x2 %0, %1, %2, %0;" : "+d"(d) : "d"(a), "d"(b));
}
__device__ __forceinline__ float2 unpk(double d) {
    float2 v;
    asm("mov.b64 {%0, %1}, %2;" : "=f"(v.x), "=f"(v.y) : "d"(d));
    return v;
}

extern __shared__ float4 smem4[];

__global__ __launch_bounds__(THREADS, 2) void cost_volume_kernel(
    const float* __restrict__ x1,
    const float* __restrict__ x2,
    float* __restrict__ out)
{
    const int tx = threadIdx.x;           // 0..7
    const int ty = threadIdx.y;           // 0..3
    const int tz = threadIdx.z;           // 0..8
    const int tid = tx + 8 * ty + 32 * tz;

    const int w0 = blockIdx.x * TW;
    const int h0 = blockIdx.y * TH;
    const int b  = blockIdx.z;

    const int h  = h0 + ty;
    const int wb = w0 + tx * 8;
    const int r2 = ty + 8 - tz;           // x2 tile row for this thread's i

    const uint32_t smem_base = (uint32_t)__cvta_generic_to_shared(smem4);

    // ---- staging setup: x2 = 864 granules (3*288), x1 = 256 ----------------
    const float* gp[3];
    uint32_t so[3];
    uint32_t ss[3];
#pragma unroll
    for (int u = 0; u < 3; u++) {
        const int gi  = tid + u * THREADS;
        const int row = gi / 18;
        const int cg  = gi - row * 18;
        so[u] = (uint32_t)((row * RS2G + swz(cg)) * 16);
        const int c  = row / TH8;
        const int r  = row - c * TH8;
        const int gh = h0 - 4 + r;
        const int gw = w0 - 4 + cg * 4;
        const bool v = (gh >= 0) && (gh < H_DIM) && (gw >= 0) && (gw <= W_DIM - 4);
        ss[u] = v ? 16u : 0u;
        gp[u] = x2 + (v ? ((((long)b * C_DIM + c) * H_DIM + gh) * W_DIM + gw) : 0);
    }
    const bool hasx1 = (tid < 256);
    const int  xrow  = tid >> 4;
    const int  xcg   = tid & 15;
    const uint32_t sox = (uint32_t)((X2_GRAN + xrow * RS1G + swz(xcg)) * 16);
    const int  xc  = xrow >> 2;
    const int  xhr = xrow & 3;
    const float* gpx = x1 + ((((long)b * C_DIM + xc) * H_DIM + (h0 + xhr)) * W_DIM + (w0 + xcg * 4));

    // thread-constant byte offsets (within a buffer) for compute-side loads
    const uint32_t woff0 = (uint32_t)(r2 * RS2G + swz(2 * tx + 0)) * 16u;
    const uint32_t woff1 = (uint32_t)(r2 * RS2G + swz(2 * tx + 1)) * 16u;
    const uint32_t woff2 = (uint32_t)(r2 * RS2G + swz(2 * tx + 2)) * 16u;
    const uint32_t woff3 = (uint32_t)(r2 * RS2G + swz(2 * tx + 3)) * 16u;
    const uint32_t aoff0 = (uint32_t)(X2_GRAN + ty * RS1G + swz(2 * tx + 0)) * 16u;
    const uint32_t aoff1 = (uint32_t)(X2_GRAN + ty * RS1G + swz(2 * tx + 1)) * 16u;

    // ---- accumulators ------------------------------------------------------
    double acc[9][4];
#pragma unroll
    for (int jj = 0; jj < 9; jj++)
#pragma unroll
        for (int t = 0; t < 4; t++)
            acc[jj][t] = 0.0;

#define STAGE(BUFI)                                                              \
    do {                                                                         \
        const uint32_t sb_ = smem_base + (uint32_t)(BUFI) * SST_BYTES;           \
        asm volatile("cp.async.cg.shared.global [%0], [%1], 16, %2;\n"           \
                     :: "r"(sb_ + so[0]), "l"(gp[0]), "r"(ss[0]));               \
        asm volatile("cp.async.cg.shared.global [%0], [%1], 16, %2;\n"           \
                     :: "r"(sb_ + so[1]), "l"(gp[1]), "r"(ss[1]));               \
        asm volatile("cp.async.cg.shared.global [%0], [%1], 16, %2;\n"           \
                     :: "r"(sb_ + so[2]), "l"(gp[2]), "r"(ss[2]));               \
        if (hasx1)                                                               \
            asm volatile("cp.async.cg.shared.global [%0], [%1], 16;\n"           \
                         :: "r"(sb_ + sox), "l"(gpx));                           \
        gp[0] += CHUNK_STRIDE; gp[1] += CHUNK_STRIDE; gp[2] += CHUNK_STRIDE;     \
        gpx += CHUNK_STRIDE;                                                     \
    } while (0)

    // ---- prologue ----------------------------------------------------------
    STAGE(0);
    asm volatile("cp.async.commit_group;" ::: "memory");
    STAGE(1);
    asm volatile("cp.async.commit_group;" ::: "memory");

    // ---- main loop ---------------------------------------------------------
    int bi = 0;
    int pi = 2;
    for (int ch = 0; ch < NCHUNK; ch++) {
        asm volatile("cp.async.wait_group 1;" ::: "memory");
        __syncthreads();

        if (ch + 2 < NCHUNK) STAGE(pi);
        asm volatile("cp.async.commit_group;" ::: "memory");

        const uint32_t bufb = smem_base + (uint32_t)bi * SST_BYTES;
#pragma unroll
        for (int c = 0; c < CC; c++) {
            const uint32_t wb_ = bufb + (uint32_t)(c * TH8 * RS2G) * 16u;
            const uint32_t ab_ = bufb + (uint32_t)(c * TH * RS1G) * 16u;

            double Ap0, Ap1, Ap2, Ap3;
            lds2(Ap0, Ap1, ab_ + aoff0);
            lds2(Ap2, Ap3, ab_ + aoff1);

            double e[8];
            lds2(e[0], e[1], wb_ + woff0);
            lds2(e[2], e[3], wb_ + woff1);
            lds2(e[4], e[5], wb_ + woff2);
            lds2(e[6], e[7], wb_ + woff3);

            // even jj: operands straight from loads
#pragma unroll
            for (int jj = 0; jj < 9; jj += 2) {
                const int m = jj >> 1;
                fma2(acc[jj][0], Ap0, e[m + 0]);
                fma2(acc[jj][1], Ap1, e[m + 1]);
                fma2(acc[jj][2], Ap2, e[m + 2]);
                fma2(acc[jj][3], Ap3, e[m + 3]);
            }

            // odd straddle-pairs, built once per channel
            double O[7];
#pragma unroll
            for (int m = 0; m < 7; m++) O[m] = dshift(e[m], e[m + 1]);

#pragma unroll
            for (int jj = 1; jj < 9; jj += 2) {
                const int m = jj >> 1;
                fma2(acc[jj][0], Ap0, O[m + 0]);
                fma2(acc[jj][1], Ap1, O[m + 1]);
                fma2(acc[jj][2], Ap2, O[m + 2]);
                fma2(acc[jj][3], Ap3, O[m + 3]);
            }
        }

        bi = (bi + 1 == NBUF) ? 0 : bi + 1;
        pi = (pi + 1 == NBUF) ? 0 : pi + 1;
    }

    // ---- epilogue ----------------------------------------------------------
    const float invD = (float)(1.0 / 81.0);
    const int i_d = tz - 4;
#pragma unroll
    for (int jj = 0; jj < 9; jj++) {
        const int j_d = 4 - jj;
        int k = 9 * i_d + j_d;
        k %= D_DIM;
        if (k < 0) k += D_DIM;

        float* op = out + ((((long)b * D_DIM + k) * H_DIM + h) * W_DIM + wb);
        const float2 p0 = unpk(acc[jj][0]);
        const float2 p1 = unpk(acc[jj][1]);
        const float2 p2 = unpk(acc[jj][2]);
        const float2 p3 = unpk(acc[jj][3]);
        ((float4*)op)[0] = make_float4(p0.x * invD, p0.y * invD, p1.x * invD, p1.y * invD);
        ((float4*)op)[1] = make_float4(p2.x * invD, p2.y * invD, p3.x * invD, p3.y * invD);
    }
}

extern "C" void kernel_launch(void* const* d_in, const int* in_sizes, int n_in,
                              void* d_out, int out_size)
{
    const float* x1 = (const float*)d_in[0];
    const float* x2 = (const float*)d_in[1];
    float* out = (float*)d_out;

    cudaFuncSetAttribute(cost_volume_kernel,
                         cudaFuncAttributeMaxDynamicSharedMemorySize, SMEM_BYTES);

    dim3 block(8, TH, 9);                       // 288 threads
    dim3 grid(W_DIM / TW, H_DIM / TH, 4);       // 512 blocks
    cost_volume_kernel<<<grid, block, SMEM_BYTES>>>(x1, x2, out);
}

// round 10
// speedup vs baseline: 1.2812x; 1.1997x over previous
#include <cuda_runtime.h>
#include <cstdint>

// CostVolume: B=4, C=128, H=128, W=256, r=4, D=81
// out[b,k,h,w] = (1/81) * sum_c x1[b,c,h,w] * x2[b,c,h-i,w-j],  k=(9i+j) mod 81
//
// Block (8,4,9). Plain scalar FFMA (no asm): acc[9][8] floats/thread.
// 3-buffer cp.async pipeline, XOR-swizzled conflict-free smem.

#define C_DIM 128
#define H_DIM 128
#define W_DIM 256
#define D_DIM 81

#define TH 4
#define TW 64
#define TH8 12
#define CC 4
#define NCHUNK 32
#define THREADS 288

#define RS2G 24                       // x2 row stride in 16B granules
#define RS1G 16                       // x1 row stride in granules
#define X2_GRAN (CC * TH8 * RS2G)     // 1152
#define X1_GRAN (CC * TH * RS1G)      // 256
#define SST_GRAN (X2_GRAN + X1_GRAN)  // 1408 granules = 22528 B
#define SST_BYTES (SST_GRAN * 16)
#define NBUF 3
#define SMEM_BYTES (NBUF * SST_BYTES) // 67584 B
#define CHUNK_STRIDE (CC * H_DIM * W_DIM)

static_assert(SMEM_BYTES <= 227 * 1024, "smem over budget");

__device__ __forceinline__ int swz(int cg) { return cg ^ ((cg >> 3) & 1); }

extern __shared__ float4 smem4[];

__global__ __launch_bounds__(THREADS, 2) void cost_volume_kernel(
    const float* __restrict__ x1,
    const float* __restrict__ x2,
    float* __restrict__ out)
{
    const int tx = threadIdx.x;           // 0..7
    const int ty = threadIdx.y;           // 0..3
    const int tz = threadIdx.z;           // 0..8
    const int tid = tx + 8 * ty + 32 * tz;

    const int w0 = blockIdx.x * TW;
    const int h0 = blockIdx.y * TH;
    const int b  = blockIdx.z;

    const int h  = h0 + ty;
    const int wb = w0 + tx * 8;
    const int r2 = ty + 8 - tz;           // x2 tile row for this thread's i

    const uint32_t smem_base = (uint32_t)__cvta_generic_to_shared(smem4);

    // ---- staging setup: x2 = 864 granules (3*288), x1 = 256 ----------------
    const float* gp[3];
    uint32_t so[3];
    uint32_t ss[3];
#pragma unroll
    for (int u = 0; u < 3; u++) {
        const int gi  = tid + u * THREADS;
        const int row = gi / 18;
        const int cg  = gi - row * 18;
        so[u] = (uint32_t)((row * RS2G + swz(cg)) * 16);
        const int c  = row / TH8;
        const int r  = row - c * TH8;
        const int gh = h0 - 4 + r;
        const int gw = w0 - 4 + cg * 4;
        const bool v = (gh >= 0) && (gh < H_DIM) && (gw >= 0) && (gw <= W_DIM - 4);
        ss[u] = v ? 16u : 0u;
        gp[u] = x2 + (v ? ((((long)b * C_DIM + c) * H_DIM + gh) * W_DIM + gw) : 0);
    }
    const bool hasx1 = (tid < 256);
    const int  xrow  = tid >> 4;
    const int  xcg   = tid & 15;
    const uint32_t sox = (uint32_t)((X2_GRAN + xrow * RS1G + swz(xcg)) * 16);
    const int  xc  = xrow >> 2;
    const int  xhr = xrow & 3;
    const float* gpx = x1 + ((((long)b * C_DIM + xc) * H_DIM + (h0 + xhr)) * W_DIM + (w0 + xcg * 4));

    // thread-constant swizzled granule indices for compute-side loads
    const int sq0 = swz(2 * tx + 0);
    const int sq1 = swz(2 * tx + 1);
    const int sq2 = swz(2 * tx + 2);
    const int sq3 = swz(2 * tx + 3);

    // ---- accumulators: 9 j-shifts x 8 pixels, plain floats -----------------
    float acc[9][8];
#pragma unroll
    for (int jj = 0; jj < 9; jj++)
#pragma unroll
        for (int p = 0; p < 8; p++)
            acc[jj][p] = 0.f;

#define STAGE(BUFI)                                                              \
    do {                                                                         \
        const uint32_t sb_ = smem_base + (uint32_t)(BUFI) * SST_BYTES;           \
        asm volatile("cp.async.cg.shared.global [%0], [%1], 16, %2;\n"           \
                     :: "r"(sb_ + so[0]), "l"(gp[0]), "r"(ss[0]));               \
        asm volatile("cp.async.cg.shared.global [%0], [%1], 16, %2;\n"           \
                     :: "r"(sb_ + so[1]), "l"(gp[1]), "r"(ss[1]));               \
        asm volatile("cp.async.cg.shared.global [%0], [%1], 16, %2;\n"           \
                     :: "r"(sb_ + so[2]), "l"(gp[2]), "r"(ss[2]));               \
        if (hasx1)                                                               \
            asm volatile("cp.async.cg.shared.global [%0], [%1], 16;\n"           \
                         :: "r"(sb_ + sox), "l"(gpx));                           \
        gp[0] += CHUNK_STRIDE; gp[1] += CHUNK_STRIDE; gp[2] += CHUNK_STRIDE;     \
        gpx += CHUNK_STRIDE;                                                     \
    } while (0)

    // ---- prologue ----------------------------------------------------------
    STAGE(0);
    asm volatile("cp.async.commit_group;" ::: "memory");
    STAGE(1);
    asm volatile("cp.async.commit_group;" ::: "memory");

    // ---- main loop ---------------------------------------------------------
    int bi = 0;
    int pi = 2;
    for (int ch = 0; ch < NCHUNK; ch++) {
        asm volatile("cp.async.wait_group 1;" ::: "memory");
        __syncthreads();

        if (ch + 2 < NCHUNK) STAGE(pi);
        asm volatile("cp.async.commit_group;" ::: "memory");

        const float4* buf = smem4 + (size_t)bi * SST_GRAN;
#pragma unroll
        for (int c = 0; c < CC; c++) {
            const int x1g = X2_GRAN + (c * TH + ty) * RS1G;
            const float4 A0 = buf[x1g + sq0];
            const float4 A1 = buf[x1g + sq1];

            const int x2g = (c * TH8 + r2) * RS2G;
            const float4 W0 = buf[x2g + sq0];
            const float4 W1 = buf[x2g + sq1];
            const float4 W2 = buf[x2g + sq2];
            const float4 W3 = buf[x2g + sq3];

            const float a[8] = {A0.x, A0.y, A0.z, A0.w, A1.x, A1.y, A1.z, A1.w};
            const float w[16] = {W0.x, W0.y, W0.z, W0.w, W1.x, W1.y, W1.z, W1.w,
                                 W2.x, W2.y, W2.z, W2.w, W3.x, W3.y, W3.z, W3.w};

#pragma unroll
            for (int jj = 0; jj < 9; jj++)
#pragma unroll
                for (int p = 0; p < 8; p++)
                    acc[jj][p] = fmaf(a[p], w[p + jj], acc[jj][p]);
        }

        bi = (bi + 1 == NBUF) ? 0 : bi + 1;
        pi = (pi + 1 == NBUF) ? 0 : pi + 1;
    }

    // ---- epilogue ----------------------------------------------------------
    const float invD = (float)(1.0 / 81.0);
    const int i_d = tz - 4;
#pragma unroll
    for (int jj = 0; jj < 9; jj++) {
        const int j_d = 4 - jj;
        int k = 9 * i_d + j_d;
        k %= D_DIM;
        if (k < 0) k += D_DIM;

        float* op = out + ((((long)b * D_DIM + k) * H_DIM + h) * W_DIM + wb);
        ((float4*)op)[0] = make_float4(acc[jj][0] * invD, acc[jj][1] * invD,
                                       acc[jj][2] * invD, acc[jj][3] * invD);
        ((float4*)op)[1] = make_float4(acc[jj][4] * invD, acc[jj][5] * invD,
                                       acc[jj][6] * invD, acc[jj][7] * invD);
    }
}

extern "C" void kernel_launch(void* const* d_in, const int* in_sizes, int n_in,
                              void* d_out, int out_size)
{
    const float* x1 = (const float*)d_in[0];
    const float* x2 = (const float*)d_in[1];
    float* out = (float*)d_out;

    cudaFuncSetAttribute(cost_volume_kernel,
                         cudaFuncAttributeMaxDynamicSharedMemorySize, SMEM_BYTES);

    dim3 block(8, TH, 9);                       // 288 threads
    dim3 grid(W_DIM / TW, H_DIM / TH, 4);       // 512 blocks
    cost_volume_kernel<<<grid, block, SMEM_BYTES>>>(x1, x2, out);
}

// round 13
// speedup vs baseline: 1.4758x; 1.1518x over previous
#include <cuda_runtime.h>
#include <cstdint>

// CostVolume: B=4, C=128, H=128, W=256, r=4, D=81
// out[b,k,h,w] = (1/81) * sum_c x1[b,c,h,w] * x2[b,c,h-i,w-j],  k=(9i+j) mod 81
//
// Block (16,2,9)=288: tx = 4-px group, ty = h row (TH=2), tz = row-shift i.
// acc[9][4] scalar floats -> ~75 regs -> 3 blocks/SM (27 warps).
// 3-buffer cp.async pipeline (depth 2), XOR-swizzled conflict-free smem.

#define C_DIM 128
#define H_DIM 128
#define W_DIM 256
#define D_DIM 81

#define TH 2
#define TW 64
#define TH8 10                        // TH + 8 halo rows
#define CC 4
#define NCHUNK 32
#define THREADS 288

#define RS2G 24                       // x2 row stride in 16B granules (96 floats)
#define RS1G 16                       // x1 row stride in granules (64 floats)
#define X2_GRAN (CC * TH8 * RS2G)     // 960 (layout), 720 populated rows*18
#define X1_GRAN (CC * TH * RS1G)      // 128
#define SST_GRAN (X2_GRAN + X1_GRAN)  // 1088 granules = 17408 B
#define SST_BYTES (SST_GRAN * 16)
#define NBUF 3
#define SMEM_BYTES (NBUF * SST_BYTES) // 52224 B per block (x3 blocks = 153 KB/SM)
#define CHUNK_STRIDE (CC * H_DIM * W_DIM)

static_assert(3 * SMEM_BYTES <= 227 * 1024, "smem over budget for 3 blocks/SM");

__device__ __forceinline__ int swz(int cg) { return cg ^ ((cg >> 3) & 1); }

extern __shared__ float4 smem4[];

__global__ __launch_bounds__(THREADS, 3) void cost_volume_kernel(
    const float* __restrict__ x1,
    const float* __restrict__ x2,
    float* __restrict__ out)
{
    const int tx = threadIdx.x;           // 0..15 (4 px each)
    const int ty = threadIdx.y;           // 0..1
    const int tz = threadIdx.z;           // 0..8
    const int tid = tx + 16 * ty + 32 * tz;

    const int w0 = blockIdx.x * TW;
    const int h0 = blockIdx.y * TH;
    const int b  = blockIdx.z;

    const int h  = h0 + ty;
    const int wb = w0 + tx * 4;
    const int r2 = ty + 8 - tz;           // x2 tile row for this thread's i (0..9)

    const uint32_t smem_base = (uint32_t)__cvta_generic_to_shared(smem4);

    // ---- staging setup -----------------------------------------------------
    // x2: 40 rows (c*10+r) x 18 granules = 720 granules -> slots u=0,1 (576)
    //     + first 144 threads of slot u=2.
    // x1: 8 rows x 16 granules = 128 granules -> threads 144..271 of slot u=2.
    const float* gp0; const float* gp1; const float* gp2;
    uint32_t so0, so1, so2, ss0, ss1, ss2;
    bool has2;
    {
        // slot 0 and 1: x2 granules tid, tid+288
#pragma unroll
        for (int u = 0; u < 2; u++) {
            const int gi  = tid + u * THREADS;      // 0..575
            const int row = gi / 18;
            const int cg  = gi - row * 18;
            const uint32_t so = (uint32_t)((row * RS2G + swz(cg)) * 16);
            const int c  = row / TH8;
            const int r  = row - c * TH8;
            const int gh = h0 - 4 + r;
            const int gw = w0 - 4 + cg * 4;
            const bool v = (gh >= 0) && (gh < H_DIM) && (gw >= 0) && (gw <= W_DIM - 4);
            const uint32_t ss = v ? 16u : 0u;
            const float* gp = x2 + (v ? ((((long)b * C_DIM + c) * H_DIM + gh) * W_DIM + gw) : 0);
            if (u == 0) { gp0 = gp; so0 = so; ss0 = ss; }
            else        { gp1 = gp; so1 = so; ss1 = ss; }
        }
        // slot 2: heterogeneous
        has2 = (tid < 272);
        if (tid < 144) {
            const int gi  = tid + 576;              // 576..719
            const int row = gi / 18;
            const int cg  = gi - row * 18;
            so2 = (uint32_t)((row * RS2G + swz(cg)) * 16);
            const int c  = row / TH8;
            const int r  = row - c * TH8;
            const int gh = h0 - 4 + r;
            const int gw = w0 - 4 + cg * 4;
            const bool v = (gh >= 0) && (gh < H_DIM) && (gw >= 0) && (gw <= W_DIM - 4);
            ss2 = v ? 16u : 0u;
            gp2 = x2 + (v ? ((((long)b * C_DIM + c) * H_DIM + gh) * W_DIM + gw) : 0);
        } else {
            const int xi  = tid - 144;              // 0..127 (valid when has2)
            const int xr  = (xi >> 4) & 7;          // row = c*2 + hr
            const int xcg = xi & 15;
            so2 = (uint32_t)((X2_GRAN + xr * RS1G + swz(xcg)) * 16);
            ss2 = 16u;
            const int c  = xr >> 1;
            const int hr = xr & 1;
            gp2 = x1 + ((((long)b * C_DIM + c) * H_DIM + (h0 + hr)) * W_DIM + (w0 + xcg * 4));
        }
    }

    // thread-constant swizzled granule indices for compute-side loads
    const int sq0 = swz(tx + 0);
    const int sq1 = swz(tx + 1);
    const int sq2 = swz(tx + 2);
    const int sqa = swz(tx);

    // ---- accumulators: 9 j-shifts x 4 pixels -------------------------------
    float acc[9][4];
#pragma unroll
    for (int jj = 0; jj < 9; jj++)
#pragma unroll
        for (int p = 0; p < 4; p++)
            acc[jj][p] = 0.f;

#define STAGE(BUFI)                                                              \
    do {                                                                         \
        const uint32_t sb_ = smem_base + (uint32_t)(BUFI) * SST_BYTES;           \
        asm volatile("cp.async.cg.shared.global [%0], [%1], 16, %2;\n"           \
                     :: "r"(sb_ + so0), "l"(gp0), "r"(ss0));                     \
        asm volatile("cp.async.cg.shared.global [%0], [%1], 16, %2;\n"           \
                     :: "r"(sb_ + so1), "l"(gp1), "r"(ss1));                     \
        if (has2)                                                                \
            asm volatile("cp.async.cg.shared.global [%0], [%1], 16, %2;\n"       \
                         :: "r"(sb_ + so2), "l"(gp2), "r"(ss2));                 \
        gp0 += CHUNK_STRIDE; gp1 += CHUNK_STRIDE; gp2 += CHUNK_STRIDE;           \
    } while (0)

    // ---- prologue ----------------------------------------------------------
    STAGE(0);
    asm volatile("cp.async.commit_group;" ::: "memory");
    STAGE(1);
    asm volatile("cp.async.commit_group;" ::: "memory");

    // ---- main loop ---------------------------------------------------------
    int bi = 0;
    int pi = 2;
    for (int ch = 0; ch < NCHUNK; ch++) {
        asm volatile("cp.async.wait_group 1;" ::: "memory");
        __syncthreads();

        if (ch + 2 < NCHUNK) STAGE(pi);
        asm volatile("cp.async.commit_group;" ::: "memory");

        const float4* buf = smem4 + (size_t)bi * SST_GRAN;
#pragma unroll
        for (int c = 0; c < CC; c++) {
            const int x1g = X2_GRAN + (c * TH + ty) * RS1G;
            const float4 A0 = buf[x1g + sqa];

            const int x2g = (c * TH8 + r2) * RS2G;
            const float4 W0 = buf[x2g + sq0];
            const float4 W1 = buf[x2g + sq1];
            const float4 W2 = buf[x2g + sq2];

            const float a[4]  = {A0.x, A0.y, A0.z, A0.w};
            const float w[12] = {W0.x, W0.y, W0.z, W0.w,
                                 W1.x, W1.y, W1.z, W1.w,
                                 W2.x, W2.y, W2.z, W2.w};

#pragma unroll
            for (int jj = 0; jj < 9; jj++)
#pragma unroll
                for (int p = 0; p < 4; p++)
                    acc[jj][p] = fmaf(a[p], w[p + jj], acc[jj][p]);
        }

        bi = (bi + 1 == NBUF) ? 0 : bi + 1;
        pi = (pi + 1 == NBUF) ? 0 : pi + 1;
    }

    // ---- epilogue ----------------------------------------------------------
    const float invD = (float)(1.0 / 81.0);
    const int i_d = tz - 4;
#pragma unroll
    for (int jj = 0; jj < 9; jj++) {
        const int j_d = 4 - jj;
        int k = 9 * i_d + j_d;
        k %= D_DIM;
        if (k < 0) k += D_DIM;

        float* op = out + ((((long)b * D_DIM + k) * H_DIM + h) * W_DIM + wb);
        *(float4*)op = make_float4(acc[jj][0] * invD, acc[jj][1] * invD,
                                   acc[jj][2] * invD, acc[jj][3] * invD);
    }
}

extern "C" void kernel_launch(void* const* d_in, const int* in_sizes, int n_in,
                              void* d_out, int out_size)
{
    const float* x1 = (const float*)d_in[0];
    const float* x2 = (const float*)d_in[1];
    float* out = (float*)d_out;

    cudaFuncSetAttribute(cost_volume_kernel,
                         cudaFuncAttributeMaxDynamicSharedMemorySize, SMEM_BYTES);

    dim3 block(16, TH, 9);                      // 288 threads
    dim3 grid(W_DIM / TW, H_DIM / TH, 4);       // (4, 64, 4) = 1024 blocks
    cost_volume_kernel<<<grid, block, SMEM_BYTES>>>(x1, x2, out);
}

// round 16
// speedup vs baseline: 1.5306x; 1.0371x over previous
#include <cuda_runtime.h>
#include <cstdint>

// CostVolume: B=4, C=128, H=128, W=256, r=4, D=81
// out[b,k,h,w] = (1/81) * sum_c x1[b,c,h,w] * x2[b,c,h-i,w-j],  k=(9i+j) mod 81
//
// Block (16,2,9)=288, 4 px/thread, 27 warps/SM (3 blocks).
// Mixed math: even j-shifts use fma.rn.f32x2 on pair-aligned ld.shared.v2.b64
// operands (no packing MOVs); odd j-shifts use scalar FFMA on aliased halves.
// 3-buffer cp.async pipeline, XOR-swizzled conflict-free smem.

#define C_DIM 128
#define H_DIM 128
#define W_DIM 256
#define D_DIM 81

#define TH 2
#define TW 64
#define TH8 10
#define CC 4
#define NCHUNK 32
#define THREADS 288

#define RS2G 24                       // x2 row stride in 16B granules
#define RS1G 16                       // x1 row stride in granules
#define X2_GRAN (CC * TH8 * RS2G)     // 960
#define X1_GRAN (CC * TH * RS1G)      // 128
#define SST_GRAN (X2_GRAN + X1_GRAN)  // 1088 granules = 17408 B
#define SST_BYTES (SST_GRAN * 16)
#define NBUF 3
#define SMEM_BYTES (NBUF * SST_BYTES) // 52224 B
#define CHUNK_STRIDE (CC * H_DIM * W_DIM)

static_assert(3 * SMEM_BYTES <= 227 * 1024, "smem over budget for 3 blocks/SM");

__device__ __forceinline__ int swz(int cg) { return cg ^ ((cg >> 3) & 1); }

// one LDS.128 -> two pair-aligned f32x2 operands
__device__ __forceinline__ void lds2(double& a, double& b, uint32_t addr) {
    asm("ld.shared.v2.b64 {%0, %1}, [%2];" : "=d"(a), "=d"(b) : "r"(addr));
}
__device__ __forceinline__ void fma2(double& d, double a, double b) {
    asm("fma.rn.f32x2 %0, %1, %2, %0;" : "+d"(d) : "d"(a), "d"(b));
}
__device__ __forceinline__ float2 unpk(double d) {
    float2 v;
    asm("mov.b64 {%0, %1}, %2;" : "=f"(v.x), "=f"(v.y) : "d"(d));
    return v;
}

extern __shared__ float4 smem4[];

__global__ __launch_bounds__(THREADS, 3) void cost_volume_kernel(
    const float* __restrict__ x1,
    const float* __restrict__ x2,
    float* __restrict__ out)
{
    const int tx = threadIdx.x;           // 0..15
    const int ty = threadIdx.y;           // 0..1
    const int tz = threadIdx.z;           // 0..8
    const int tid = tx + 16 * ty + 32 * tz;

    const int w0 = blockIdx.x * TW;
    const int h0 = blockIdx.y * TH;
    const int b  = blockIdx.z;

    const int h  = h0 + ty;
    const int wb = w0 + tx * 4;
    const int r2 = ty + 8 - tz;           // x2 tile row (0..9)

    const uint32_t smem_base = (uint32_t)__cvta_generic_to_shared(smem4);

    // ---- staging setup (same proven layout as R12) --------------------------
    const float* gp0; const float* gp1; const float* gp2;
    uint32_t so0, so1, so2, ss0, ss1, ss2;
    bool has2;
    {
#pragma unroll
        for (int u = 0; u < 2; u++) {
            const int gi  = tid + u * THREADS;
            const int row = gi / 18;
            const int cg  = gi - row * 18;
            const uint32_t so = (uint32_t)((row * RS2G + swz(cg)) * 16);
            const int c  = row / TH8;
            const int r  = row - c * TH8;
            const int gh = h0 - 4 + r;
            const int gw = w0 - 4 + cg * 4;
            const bool v = (gh >= 0) && (gh < H_DIM) && (gw >= 0) && (gw <= W_DIM - 4);
            const uint32_t ss = v ? 16u : 0u;
            const float* gp = x2 + (v ? ((((long)b * C_DIM + c) * H_DIM + gh) * W_DIM + gw) : 0);
            if (u == 0) { gp0 = gp; so0 = so; ss0 = ss; }
            else        { gp1 = gp; so1 = so; ss1 = ss; }
        }
        has2 = (tid < 272);
        if (tid < 144) {
            const int gi  = tid + 576;
            const int row = gi / 18;
            const int cg  = gi - row * 18;
            so2 = (uint32_t)((row * RS2G + swz(cg)) * 16);
            const int c  = row / TH8;
            const int r  = row - c * TH8;
            const int gh = h0 - 4 + r;
            const int gw = w0 - 4 + cg * 4;
            const bool v = (gh >= 0) && (gh < H_DIM) && (gw >= 0) && (gw <= W_DIM - 4);
            ss2 = v ? 16u : 0u;
            gp2 = x2 + (v ? ((((long)b * C_DIM + c) * H_DIM + gh) * W_DIM + gw) : 0);
        } else {
            const int xi  = tid - 144;
            const int xr  = (xi >> 4) & 7;
            const int xcg = xi & 15;
            so2 = (uint32_t)((X2_GRAN + xr * RS1G + swz(xcg)) * 16);
            ss2 = 16u;
            const int c  = xr >> 1;
            const int hr = xr & 1;
            gp2 = x1 + ((((long)b * C_DIM + c) * H_DIM + (h0 + hr)) * W_DIM + (w0 + xcg * 4));
        }
    }

    // compute-side byte offsets (within buffer)
    const uint32_t woff0 = (uint32_t)(r2 * RS2G + swz(tx + 0)) * 16u;
    const uint32_t woff1 = (uint32_t)(r2 * RS2G + swz(tx + 1)) * 16u;
    const uint32_t woff2 = (uint32_t)(r2 * RS2G + swz(tx + 2)) * 16u;
    const uint32_t aoff  = (uint32_t)(X2_GRAN + ty * RS1G + swz(tx)) * 16u;

    // ---- accumulators: 5 even jj as f32x2 pairs, 4 odd jj as scalars --------
    double accP[5][2];                    // jj = 0,2,4,6,8
    float  accS[4][4];                    // jj = 1,3,5,7
#pragma unroll
    for (int m = 0; m < 5; m++) { accP[m][0] = 0.0; accP[m][1] = 0.0; }
#pragma unroll
    for (int m = 0; m < 4; m++)
#pragma unroll
        for (int p = 0; p < 4; p++) accS[m][p] = 0.f;

#define STAGE(BUFI)                                                              \
    do {                                                                         \
        const uint32_t sb_ = smem_base + (uint32_t)(BUFI) * SST_BYTES;           \
        asm volatile("cp.async.cg.shared.global [%0], [%1], 16, %2;\n"           \
                     :: "r"(sb_ + so0), "l"(gp0), "r"(ss0));                     \
        asm volatile("cp.async.cg.shared.global [%0], [%1], 16, %2;\n"           \
                     :: "r"(sb_ + so1), "l"(gp1), "r"(ss1));                     \
        if (has2)                                                                \
            asm volatile("cp.async.cg.shared.global [%0], [%1], 16, %2;\n"       \
                         :: "r"(sb_ + so2), "l"(gp2), "r"(ss2));                 \
        gp0 += CHUNK_STRIDE; gp1 += CHUNK_STRIDE; gp2 += CHUNK_STRIDE;           \
    } while (0)

    // ---- prologue ----------------------------------------------------------
    STAGE(0);
    asm volatile("cp.async.commit_group;" ::: "memory");
    STAGE(1);
    asm volatile("cp.async.commit_group;" ::: "memory");

    // ---- main loop ---------------------------------------------------------
    int bi = 0;
    int pi = 2;
    for (int ch = 0; ch < NCHUNK; ch++) {
        asm volatile("cp.async.wait_group 1;" ::: "memory");
        __syncthreads();

        if (ch + 2 < NCHUNK) STAGE(pi);
        asm volatile("cp.async.commit_group;" ::: "memory");

        const uint32_t bufb = smem_base + (uint32_t)bi * SST_BYTES;
#pragma unroll
        for (int c = 0; c < CC; c++) {
            const uint32_t wbase = bufb + (uint32_t)(c * TH8 * RS2G) * 16u;
            const uint32_t abase = bufb + (uint32_t)(c * TH * RS1G) * 16u;

            // x1: 4 px as 2 pairs
            double a01, a23;
            lds2(a01, a23, abase + aoff);

            // window: 12 floats as 6 even-aligned pairs e[q] = (w[2q], w[2q+1])
            double e[6];
            lds2(e[0], e[1], wbase + woff0);
            lds2(e[2], e[3], wbase + woff1);
            lds2(e[4], e[5], wbase + woff2);

            // even jj = 2m: acc pairs directly from loaded pairs
#pragma unroll
            for (int m = 0; m < 5; m++) {
                fma2(accP[m][0], a01, e[m + 0]);
                fma2(accP[m][1], a23, e[m + 1]);
            }

            // odd jj = 2m+1: scalar FFMA on register halves (free aliasing)
            const float2 a0 = unpk(a01), a1 = unpk(a23);
            const float av[4] = {a0.x, a0.y, a1.x, a1.y};
            float wv[12];
#pragma unroll
            for (int q = 0; q < 6; q++) {
                const float2 t = unpk(e[q]);
                wv[2 * q] = t.x; wv[2 * q + 1] = t.y;
            }
#pragma unroll
            for (int m = 0; m < 4; m++) {
                const int jj = 2 * m + 1;
#pragma unroll
                for (int p = 0; p < 4; p++)
                    accS[m][p] = fmaf(av[p], wv[p + jj], accS[m][p]);
            }
        }

        bi = (bi + 1 == NBUF) ? 0 : bi + 1;
        pi = (pi + 1 == NBUF) ? 0 : pi + 1;
    }

    // ---- epilogue ----------------------------------------------------------
    const float invD = (float)(1.0 / 81.0);
    const int i_d = tz - 4;

    // even jj
#pragma unroll
    for (int m = 0; m < 5; m++) {
        const int jj = 2 * m;
        const int j_d = 4 - jj;
        int k = 9 * i_d + j_d;
        k %= D_DIM;
        if (k < 0) k += D_DIM;
        float* op = out + ((((long)b * D_DIM + k) * H_DIM + h) * W_DIM + wb);
        const float2 p0 = unpk(accP[m][0]);
        const float2 p1 = unpk(accP[m][1]);
        *(float4*)op = make_float4(p0.x * invD, p0.y * invD, p1.x * invD, p1.y * invD);
    }
    // odd jj
#pragma unroll
    for (int m = 0; m < 4; m++) {
        const int jj = 2 * m + 1;
        const int j_d = 4 - jj;
        int k = 9 * i_d + j_d;
        k %= D_DIM;
        if (k < 0) k += D_DIM;
        float* op = out + ((((long)b * D_DIM + k) * H_DIM + h) * W_DIM + wb);
        *(float4*)op = make_float4(accS[m][0] * invD, accS[m][1] * invD,
                                   accS[m][2] * invD, accS[m][3] * invD);
    }
}

extern "C" void kernel_launch(void* const* d_in, const int* in_sizes, int n_in,
                              void* d_out, int out_size)
{
    const float* x1 = (const float*)d_in[0];
    const float* x2 = (const float*)d_in[1];
    float* out = (float*)d_out;

    cudaFuncSetAttribute(cost_volume_kernel,
                         cudaFuncAttributeMaxDynamicSharedMemorySize, SMEM_BYTES);

    dim3 block(16, TH, 9);                      // 288 threads
    dim3 grid(W_DIM / TW, H_DIM / TH, 4);       // 1024 blocks
    cost_volume_kernel<<<grid, block, SMEM_BYTES>>>(x1, x2, out);
}